// round 5
// baseline (speedup 1.0000x reference)
#include <cuda_runtime.h>

// Sparse CG tensor product:
//   out[b, M[i]] += scale[i] * x[b, M1[i]] * y[b, M2[i]]
//
// One CTA = 32 batch rows, 32 warps (1024 threads). Tiles in smem as
// [32 rows][stride 513]. Gather addr = lane*513 + m => bank
// (lane + m) mod 32: a permutation over lanes => conflict-free.
// Rows are not 16B-aligned (odd stride) => all tile fill/drain is scalar,
// lane -> consecutive d (conflict-free in smem, coalesced in GMEM).
// All 32 lanes of a warp process the SAME path => metadata is one broadcast
// LDS.128. M sorted => register accumulation, one smem store per column
// change; per-warp path ranges are segment-aligned => single writer per
// output column, no atomics.

#define DIMC    512
#define STRIDE  513
#define TILE    (32 * STRIDE)          // 16416 floats
#define NWARP   32
#define NTHR    (NWARP * 32)           // 1024
#define CHUNK   32
#define MAXNNZ  8192

__device__ int4 g_paths[MAXNNZ];       // {M, M1, M2, bits(scale)} (raw indices)
__device__ int  g_wstart[NWARP + 1];

// ---------------------------------------------------------------------------
__global__ void pack_kernel(const float* __restrict__ scale,
                            const int* __restrict__ M,
                            const int* __restrict__ M1,
                            const int* __restrict__ M2,
                            int nnz)
{
    int i = blockIdx.x * blockDim.x + threadIdx.x;
    if (i < nnz) {
        g_paths[i] = make_int4(M[i], M1[i], M2[i], __float_as_int(scale[i]));
    }
    if (i == 0) {
        g_wstart[0] = 0;
        g_wstart[NWARP] = nnz;
        int prev = 0;
        for (int w = 1; w < NWARP; w++) {
            int t = (int)(((long long)w * nnz) / NWARP);
            if (t < prev) t = prev;
            while (t > 0 && t < nnz && M[t] == M[t - 1]) t++;  // segment align
            g_wstart[w] = t;
            prev = t;
        }
    }
}

// ---------------------------------------------------------------------------
__global__ __launch_bounds__(NTHR, 1)
void tp_kernel(const float* __restrict__ x,
               const float* __restrict__ y,
               float* __restrict__ out,
               int Brows)
{
    extern __shared__ float sm[];
    float* xs = sm;                          // [32][STRIDE]
    float* ys = sm + TILE;
    float* os = sm + 2 * TILE;
    int4*  spath = (int4*)(sm + 3 * TILE);   // [NWARP][CHUNK]

    const int tid  = threadIdx.x;
    const int lane = tid & 31;
    const int warp = tid >> 5;
    const int b0   = blockIdx.x << 5;
    const int nb   = min(32, Brows - b0);

    // ---- fill tiles + zero output tile (scalar, conflict-free, coalesced) ----
    if (nb == 32) {
        const int gbase = b0 * DIMC;         // fits in int (B*DIM ~ 10.2M)
        #pragma unroll 4
        for (int it = 0; it < (32 * DIMC) / NTHR; it++) {
            int idx = it * NTHR + tid;
            int b = idx >> 9;
            int d = idx & 511;
            int g = gbase + idx;
            int s = b * STRIDE + d;
            xs[s] = x[g];
            ys[s] = y[g];
            os[s] = 0.f;
        }
    } else {
        for (int idx = tid; idx < 32 * DIMC; idx += NTHR) {
            int b = idx >> 9;
            int d = idx & 511;
            float vx = 0.f, vy = 0.f;
            if (b < nb) {
                int g = (b0 + b) * DIMC + d;
                vx = x[g];
                vy = y[g];
            }
            int s = b * STRIDE + d;
            xs[s] = vx;
            ys[s] = vy;
            os[s] = 0.f;
        }
    }
    __syncthreads();

    // ---- per-warp path processing ----
    const int istart = g_wstart[warp];
    const int iend   = g_wstart[warp + 1];

    if (istart < iend) {
        int4* sp = spath + warp * CHUNK;
        const float* xsl = xs + lane * STRIDE;
        const float* ysl = ys + lane * STRIDE;
        float*       osl = os + lane * STRIDE;

        // prefetch chunk 0 (coalesced LDG.128)
        int4 r0;
        {
            int i0 = istart + lane;
            r0 = (i0 < iend) ? g_paths[i0] : make_int4(0, 0, 0, 0);
        }

        float acc  = 0.f;
        int   mcur = __shfl_sync(0xffffffffu, r0.x, 0);

        for (int base = istart; base < iend; base += CHUNK) {
            sp[lane] = r0;
            __syncwarp();

            // prefetch next chunk (overlaps processing)
            {
                int i0 = base + CHUNK + lane;
                r0 = (i0 < iend) ? g_paths[i0] : make_int4(0, 0, 0, 0);
            }

            const int cnt = min(CHUNK, iend - base);
            #pragma unroll 4
            for (int j = 0; j < cnt; j++) {
                int4 p = sp[j];                 // broadcast LDS.128
                if (p.x != mcur) {              // warp-uniform
                    osl[mcur] = acc;            // single owner, no atomic
                    acc  = 0.f;
                    mcur = p.x;
                }
                acc = fmaf(__int_as_float(p.w) * xsl[p.y], ysl[p.z], acc);
            }
            __syncwarp();
        }
        osl[mcur] = acc;                        // final flush
    }
    __syncthreads();

    // ---- drain output tile (scalar LDS, coalesced STG) ----
    if (nb == 32) {
        const int gbase = b0 * DIMC;
        #pragma unroll 4
        for (int it = 0; it < (32 * DIMC) / NTHR; it++) {
            int idx = it * NTHR + tid;
            int b = idx >> 9;
            int d = idx & 511;
            out[gbase + idx] = os[b * STRIDE + d];
        }
    } else {
        for (int idx = tid; idx < 32 * DIMC; idx += NTHR) {
            int b = idx >> 9;
            int d = idx & 511;
            if (b < nb) out[(b0 + b) * DIMC + d] = os[b * STRIDE + d];
        }
    }
}

// ---------------------------------------------------------------------------
extern "C" void kernel_launch(void* const* d_in, const int* in_sizes, int n_in,
                              void* d_out, int out_size)
{
    const float* x     = (const float*)d_in[0];
    const float* y     = (const float*)d_in[1];
    const float* scale = (const float*)d_in[2];
    const int*   M     = (const int*)d_in[3];
    const int*   M1    = (const int*)d_in[4];
    const int*   M2    = (const int*)d_in[5];
    float*       out   = (float*)d_out;

    const int B   = in_sizes[0] / DIMC;
    const int nnz = in_sizes[2];

    const size_t smem_bytes = (size_t)3 * TILE * sizeof(float)
                            + (size_t)NWARP * CHUNK * sizeof(int4); // 213376 B
    cudaFuncSetAttribute(tp_kernel, cudaFuncAttributeMaxDynamicSharedMemorySize,
                         (int)smem_bytes);

    pack_kernel<<<(nnz + 255) / 256, 256>>>(scale, M, M1, M2, nnz);

    const int nblocks = (B + 31) / 32;
    tp_kernel<<<nblocks, NTHR, smem_bytes>>>(x, y, out, B);
}